// round 1
// baseline (speedup 1.0000x reference)
#include <cuda_runtime.h>

// Problem constants (fixed shapes from setup_inputs)
#define RR 4
#define ND 81
#define NB 4
#define NC 128
#define NH 96
#define NW 160

// Tiling
#define TX 80               // x-tile per block
#define YB 2                // y-rows per block
#define PX 8                // pixels per thread (x)
#define XG (TX / PX)        // 10 x-groups
#define NTHREADS (XG * 9 * YB)  // 180
#define CCHUNK 8            // channels per smem stage
#define TGT_W (TX + 2 * RR) // 88
#define TGT_H (YB + 2 * RR) // 10

// Map (dy,dx) -> output displacement channel, matching the reference's
// _displacements(4) ordering:
//   0:(0,0); for i=1..4: (-i,0),(i,0),(0,-i),(0,i) then for j=1..4:
//   (-i,-j),(i,j),(-i,j),(i,-j)
__device__ __forceinline__ int disp_index(int dyv, int dxv) {
    int ay = dyv < 0 ? -dyv : dyv;
    int ax = dxv < 0 ? -dxv : dxv;
    if ((ay | ax) == 0) return 0;
    if (ax == 0) return 1 + (ay - 1) * 20 + (dyv < 0 ? 0 : 1);
    if (ay == 0) return 1 + (ax - 1) * 20 + (dxv < 0 ? 2 : 3);
    int base = 1 + (ay - 1) * 20 + 4 + (ax - 1) * 4;
    if (dyv < 0 && dxv < 0) return base + 0;
    if (dyv > 0 && dxv > 0) return base + 1;
    if (dyv < 0 && dxv > 0) return base + 2;
    return base + 3;   // dyv>0 && dxv<0
}

__global__ __launch_bounds__(NTHREADS, 2)
void costvol_kernel(const float* __restrict__ src,
                    const float* __restrict__ tgt,
                    float* __restrict__ out) {
    __shared__ float s_src[CCHUNK][YB][TX];
    __shared__ float s_tgt[CCHUNK][TGT_H][TGT_W];

    const int tid = threadIdx.x;
    const int xg  = tid % XG;
    const int dyi = (tid / XG) % 9;
    const int yr  = tid / (XG * 9);
    const int dyv = dyi - RR;

    const int x0 = blockIdx.x * TX;
    const int y0 = blockIdx.y * YB;
    const int b  = blockIdx.z;

    float acc[9][PX];
#pragma unroll
    for (int i = 0; i < 9; i++)
#pragma unroll
        for (int p = 0; p < PX; p++) acc[i][p] = 0.0f;

    const float* srcB = src + (long)b * NC * NH * NW;
    const float* tgtB = tgt + (long)b * NC * NH * NW;

    const int trow = yr + dyv + RR;   // 0..9

    for (int c0 = 0; c0 < NC; c0 += CCHUNK) {
        __syncthreads();
        // --- stage src: CCHUNK * YB * TX floats ---
        for (int idx = tid; idx < CCHUNK * YB * TX; idx += NTHREADS) {
            int cc  = idx / (YB * TX);
            int rem = idx % (YB * TX);
            int ry  = rem / TX;
            int xx  = rem % TX;
            s_src[cc][ry][xx] =
                srcB[(((c0 + cc) * NH) + (y0 + ry)) * NW + x0 + xx];
        }
        // --- stage tgt (with halo, zero-padded): CCHUNK * TGT_H * TGT_W ---
        for (int idx = tid; idx < CCHUNK * TGT_H * TGT_W; idx += NTHREADS) {
            int cc  = idx / (TGT_H * TGT_W);
            int rem = idx % (TGT_H * TGT_W);
            int r   = rem / TGT_W;
            int xs  = rem % TGT_W;
            int gy  = y0 + r - RR;
            int gx  = x0 + xs - RR;
            float v = 0.0f;
            if ((unsigned)gy < (unsigned)NH && (unsigned)gx < (unsigned)NW)
                v = tgtB[(((c0 + cc) * NH) + gy) * NW + gx];
            s_tgt[cc][r][xs] = v;
        }
        __syncthreads();

        // --- compute: per channel, 8 src + 16 tgt regs feed 72 FMAs ---
#pragma unroll
        for (int cc = 0; cc < CCHUNK; cc++) {
            const float4 s0 = *(const float4*)&s_src[cc][yr][xg * PX];
            const float4 s1 = *(const float4*)&s_src[cc][yr][xg * PX + 4];
            const float4* tp = (const float4*)&s_tgt[cc][trow][xg * PX];
            const float4 t0 = tp[0], t1 = tp[1], t2 = tp[2], t3 = tp[3];

            float s[PX] = {s0.x, s0.y, s0.z, s0.w, s1.x, s1.y, s1.z, s1.w};
            float t[16] = {t0.x, t0.y, t0.z, t0.w, t1.x, t1.y, t1.z, t1.w,
                           t2.x, t2.y, t2.z, t2.w, t3.x, t3.y, t3.z, t3.w};
#pragma unroll
            for (int dxi = 0; dxi < 9; dxi++)
#pragma unroll
                for (int p = 0; p < PX; p++)
                    acc[dxi][p] = fmaf(s[p], t[p + dxi], acc[dxi][p]);
        }
    }

    // --- epilogue: scale by 1/81 and scatter to displacement channels ---
    const float inv = 1.0f / 81.0f;
    const int y = y0 + yr;
#pragma unroll
    for (int dxi = 0; dxi < 9; dxi++) {
        int d = disp_index(dyv, dxi - RR);
        float* o = out + ((((long)b * ND + d) * NH) + y) * NW + x0 + xg * PX;
        float4 v0 = make_float4(acc[dxi][0] * inv, acc[dxi][1] * inv,
                                acc[dxi][2] * inv, acc[dxi][3] * inv);
        float4 v1 = make_float4(acc[dxi][4] * inv, acc[dxi][5] * inv,
                                acc[dxi][6] * inv, acc[dxi][7] * inv);
        *(float4*)o = v0;
        *((float4*)o + 1) = v1;
    }
}

extern "C" void kernel_launch(void* const* d_in, const int* in_sizes, int n_in,
                              void* d_out, int out_size) {
    const float* src = (const float*)d_in[0];
    const float* tgt = (const float*)d_in[1];
    float* out = (float*)d_out;

    dim3 grid(NW / TX, NH / YB, NB);   // (2, 48, 4) = 384 blocks
    dim3 block(NTHREADS);              // 180 threads
    costvol_kernel<<<grid, block>>>(src, tgt, out);
}

// round 2
// speedup vs baseline: 3.8849x; 3.8849x over previous
#include <cuda_runtime.h>
#include <cstdint>

// Problem constants
#define RR 4
#define ND 81
#define NB 4
#define NC 128
#define NH 96
#define NW 160

// Tiling
#define TX 32
#define YB 4
#define PX 4
#define XG 8                 // TX/PX
#define NDY 9
#define NTHREADS 288         // XG*NDY*YB = 9 warps exactly
#define CCHUNK 8
#define NCHUNK 16            // NC/CCHUNK
#define TGT_W (TX + 2*RR)    // 40
#define TGT_H (YB + 2*RR)    // 12
#define TGT_TILE (CCHUNK*TGT_H*TGT_W)   // 3840 floats
#define SRC_TILE (CCHUNK*YB*TX)         // 1024 floats
#define BUF_FLOATS (TGT_TILE + SRC_TILE) // 4864
#define NQUADS (BUF_FLOATS/4)            // 1216
#define MAXSLOTS 5
#define CSTRIDE (CCHUNK*NH*NW)           // float stride per channel chunk

// displacement channel order matching reference _displacements(4)
__device__ __forceinline__ int disp_index(int dyv, int dxv) {
    int ay = dyv < 0 ? -dyv : dyv;
    int ax = dxv < 0 ? -dxv : dxv;
    if ((ay | ax) == 0) return 0;
    if (ax == 0) return 1 + (ay - 1) * 20 + (dyv < 0 ? 0 : 1);
    if (ay == 0) return 1 + (ax - 1) * 20 + (dxv < 0 ? 2 : 3);
    int base = 1 + (ay - 1) * 20 + 4 + (ax - 1) * 4;
    if (dyv < 0 && dxv < 0) return base + 0;
    if (dyv > 0 && dxv > 0) return base + 1;
    if (dyv < 0 && dxv > 0) return base + 2;
    return base + 3;
}

__device__ __forceinline__ void cp_async16(uint32_t saddr, const void* gaddr, int sz) {
    asm volatile("cp.async.cg.shared.global [%0], [%1], 16, %2;\n"
                 :: "r"(saddr), "l"(gaddr), "r"(sz));
}
__device__ __forceinline__ void cp_commit() {
    asm volatile("cp.async.commit_group;\n" ::: "memory");
}

__global__ __launch_bounds__(NTHREADS, 2)
void costvol_kernel(const float* __restrict__ src,
                    const float* __restrict__ tgt,
                    float* __restrict__ out) {
    __shared__ float sm[2][BUF_FLOATS];

    const int tid = threadIdx.x;
    const int x0 = blockIdx.x * TX;
    const int y0 = blockIdx.y * YB;
    const int b  = blockIdx.z;

    const float* srcB = src + (size_t)b * NC * NH * NW;
    const float* tgtB = tgt + (size_t)b * NC * NH * NW;

    // ---- precompute staging slots (fixed for all chunks) ----
    const float* gptr[MAXSLOTS];
    uint32_t     soff[MAXSLOTS];
    int          ssz[MAXSLOTS];
#pragma unroll
    for (int k = 0; k < MAXSLOTS; k++) {
        int idx = tid + k * NTHREADS;
        if (idx < NQUADS) {
            if (idx < TGT_TILE / 4) {
                int cc  = idx / (TGT_H * TGT_W / 4);
                int rem = idx % (TGT_H * TGT_W / 4);
                int row = rem / (TGT_W / 4);
                int xq  = rem % (TGT_W / 4);
                int gy = y0 + row - RR;
                int gx = x0 + xq * 4 - RR;
                bool ok = ((unsigned)gy < NH) && ((unsigned)gx < NW);
                gptr[k] = ok ? (tgtB + ((size_t)cc * NH + gy) * NW + gx) : tgtB;
                soff[k] = (uint32_t)(((cc * TGT_H + row) * TGT_W + xq * 4) * 4);
                ssz[k]  = ok ? 16 : 0;
            } else {
                int q   = idx - TGT_TILE / 4;
                int cc  = q / (YB * TX / 4);
                int rem = q % (YB * TX / 4);
                int ry  = rem / (TX / 4);
                int xq  = rem % (TX / 4);
                gptr[k] = srcB + ((size_t)cc * NH + (y0 + ry)) * NW + x0 + xq * 4;
                soff[k] = (uint32_t)((TGT_TILE + (cc * YB + ry) * TX + xq * 4) * 4);
                ssz[k]  = 16;
            }
        }
    }

    const uint32_t smem_base = (uint32_t)__cvta_generic_to_shared(&sm[0][0]);

    // ---- compute role ----
    const int xg   = tid & (XG - 1);
    const int dyi  = (tid >> 3) % NDY;
    const int yr   = tid / (XG * NDY);
    const int dyv  = dyi - RR;
    const int trow = yr + dyi;      // 0..11

    float acc[NDY][PX];
#pragma unroll
    for (int i = 0; i < NDY; i++)
#pragma unroll
        for (int p = 0; p < PX; p++) acc[i][p] = 0.0f;

    // ---- prologue: stage chunk 0 into buf 0 ----
#pragma unroll
    for (int k = 0; k < MAXSLOTS; k++) {
        if (tid + k * NTHREADS < NQUADS) {
            cp_async16(smem_base + soff[k], gptr[k], ssz[k]);
            gptr[k] += CSTRIDE;
        }
    }
    cp_commit();

#pragma unroll 1
    for (int ch = 0; ch < NCHUNK; ch++) {
        if (ch + 1 < NCHUNK) {
            const uint32_t bofs = ((ch + 1) & 1) * (BUF_FLOATS * 4);
#pragma unroll
            for (int k = 0; k < MAXSLOTS; k++) {
                if (tid + k * NTHREADS < NQUADS) {
                    cp_async16(smem_base + bofs + soff[k], gptr[k], ssz[k]);
                    gptr[k] += CSTRIDE;
                }
            }
            cp_commit();
            asm volatile("cp.async.wait_group 1;\n" ::: "memory");
        } else {
            asm volatile("cp.async.wait_group 0;\n" ::: "memory");
        }
        __syncthreads();

        const float* bp = &sm[ch & 1][0];
        const float* tb = bp + trow * TGT_W + xg * PX;
        const float* sb = bp + TGT_TILE + yr * TX + xg * PX;
#pragma unroll
        for (int cc = 0; cc < CCHUNK; cc++) {
            float4 s4 = *(const float4*)(sb + cc * (YB * TX));
            const float4* tq = (const float4*)(tb + cc * (TGT_H * TGT_W));
            float4 t0 = tq[0], t1 = tq[1], t2 = tq[2];
            float s[PX]  = {s4.x, s4.y, s4.z, s4.w};
            float t[12]  = {t0.x, t0.y, t0.z, t0.w,
                            t1.x, t1.y, t1.z, t1.w,
                            t2.x, t2.y, t2.z, t2.w};
#pragma unroll
            for (int dx = 0; dx < NDY; dx++)
#pragma unroll
                for (int p = 0; p < PX; p++)
                    acc[dx][p] = fmaf(s[p], t[dx + p], acc[dx][p]);
        }
        __syncthreads();
    }

    // ---- epilogue: scale + scatter to displacement channels ----
    const float inv = 1.0f / 81.0f;
    const int y = y0 + yr;
#pragma unroll
    for (int dx = 0; dx < NDY; dx++) {
        int d = disp_index(dyv, dx - RR);
        float* o = out + ((((size_t)b * ND + d) * NH) + y) * NW + x0 + xg * PX;
        float4 v = make_float4(acc[dx][0] * inv, acc[dx][1] * inv,
                               acc[dx][2] * inv, acc[dx][3] * inv);
        *(float4*)o = v;
    }
}

extern "C" void kernel_launch(void* const* d_in, const int* in_sizes, int n_in,
                              void* d_out, int out_size) {
    const float* src = (const float*)d_in[0];
    const float* tgt = (const float*)d_in[1];
    float* out = (float*)d_out;

    dim3 grid(NW / TX, NH / YB, NB);   // (5, 24, 4) = 480 blocks
    dim3 block(NTHREADS);              // 288 threads = 9 warps
    costvol_kernel<<<grid, block>>>(src, tgt, out);
}